// round 6
// baseline (speedup 1.0000x reference)
#include <cuda_runtime.h>

// GraphConvolution: out[dst] = sum_e w_e * (x W + b)[src_e]
// Restructured:  agg[dst] = sum_e w_e * x[src_e];  degw[dst] = sum_e w_e
//                out = agg @ W + degw[:,None] * b[None,:]
//
// FULLY FUSED single kernel. edge_dst is SORTED, so block b owns nodes
// [b*64, b*64+64), binary-searches its edge range, aggregates into a
// 64x128 smem tile (no global scratch, no global atomics, no zero pass),
// then multiplies the tile by W (staged in smem) and writes out directly.
//
// Inputs: x[N,128] f32, W[128,128] f32, b[128] f32,
//         edge_weight[E] f32, edge_src[E] i32, edge_dst[E] i32 (sorted)
// Output: out[N,128] f32

#define D   128
#define D4  32      // D / 4
#define NB  64      // nodes per block

// smem floats: W[128*128] + agg[NB*128] + deg[NB]
#define SMEM_FLOATS (D * D + NB * D + NB)
#define SMEM_BYTES  (SMEM_FLOATS * 4)

__device__ __forceinline__ int lbound(const int* __restrict__ a, int n, int v) {
    int lo = 0, hi = n;
    while (lo < hi) {
        int mid = (lo + hi) >> 1;
        if (__ldg(a + mid) < v) lo = mid + 1; else hi = mid;
    }
    return lo;
}

__global__ void __launch_bounds__(256)
gc_fused_kernel(const float4* __restrict__ x4,
                const float*  __restrict__ W,
                const float*  __restrict__ b,
                const float*  __restrict__ ew,
                const int*    __restrict__ esrc,
                const int*    __restrict__ edst,
                float*        __restrict__ out,
                int n_nodes, int E) {
    extern __shared__ float sm[];
    float* sW   = sm;              // [128][128]
    float* sAgg = sm + D * D;      // [NB][128]
    float* sDeg = sAgg + NB * D;   // [NB]

    const int tid     = threadIdx.x;
    const int lane    = tid & 31;
    const int warp    = tid >> 5;
    const int node_lo = blockIdx.x * NB;

    // ---- stage W, zero agg tile ----
    float4* sW4 = reinterpret_cast<float4*>(sW);
    const float4* W4 = reinterpret_cast<const float4*>(W);
    for (int i = tid; i < D * D4; i += 256) sW4[i] = W4[i];
    float4* sAgg4 = reinterpret_cast<float4*>(sAgg);
    const float4 z4 = make_float4(0.f, 0.f, 0.f, 0.f);
    for (int i = tid; i < NB * D4; i += 256) sAgg4[i] = z4;
    if (tid < NB) sDeg[tid] = 0.f;

    // ---- edge range for this block's node range (all threads redundantly) ----
    const int e0 = lbound(edst, E, node_lo);
    const int e1 = lbound(edst, E, node_lo + NB);
    __syncthreads();

    // ---- phase 1: aggregation. 8 warps split [e0, e1). ----
    {
        const int total = e1 - e0;
        const int per   = (total + 7) >> 3;
        const int ws    = e0 + warp * per;
        const int we    = min(ws + per, e1);

        float4 acc  = z4;
        float  wsum = 0.f;
        int    cur  = -1;

        for (int base = ws; base < we; base += 32) {
            const int e = base + lane;
            int s = 0, d = -1;
            float w = 0.f;
            if (e < we) { s = esrc[e]; d = edst[e]; w = ew[e]; }
            const int cnt = min(32, we - base);

            for (int i = 0; i < cnt; i++) {
                const int   src = __shfl_sync(0xffffffffu, s, i);
                const int   dst = __shfl_sync(0xffffffffu, d, i);
                const float wt  = __shfl_sync(0xffffffffu, w, i);

                if (dst != cur) {
                    if (cur >= 0) {
                        float* p = sAgg + (cur - node_lo) * D + lane * 4;
                        atomicAdd(p + 0, acc.x);
                        atomicAdd(p + 1, acc.y);
                        atomicAdd(p + 2, acc.z);
                        atomicAdd(p + 3, acc.w);
                        if (lane == 0) atomicAdd(&sDeg[cur - node_lo], wsum);
                    }
                    acc  = z4;
                    wsum = 0.f;
                    cur  = dst;
                }
                const float4 v = x4[(size_t)src * D4 + lane];
                acc.x += wt * v.x;
                acc.y += wt * v.y;
                acc.z += wt * v.z;
                acc.w += wt * v.w;
                wsum  += wt;
            }
        }
        if (cur >= 0) {
            float* p = sAgg + (cur - node_lo) * D + lane * 4;
            atomicAdd(p + 0, acc.x);
            atomicAdd(p + 1, acc.y);
            atomicAdd(p + 2, acc.z);
            atomicAdd(p + 3, acc.w);
            if (lane == 0) atomicAdd(&sDeg[cur - node_lo], wsum);
        }
    }
    __syncthreads();

    // ---- phase 2: out[node_lo + 0..63] = agg @ W + deg * b ----
    // thread (warp r, lane c): rows r*8..r*8+7, cols 4c..4c+3.
    {
        const int c = lane;
        const int r = warp;

        float acc[8][4];
#pragma unroll
        for (int i = 0; i < 8; i++)
#pragma unroll
            for (int t = 0; t < 4; t++) acc[i][t] = 0.f;

#pragma unroll
        for (int k4 = 0; k4 < 32; k4++) {
            const float4 w0 = sW4[(k4 * 4 + 0) * 32 + c];
            const float4 w1 = sW4[(k4 * 4 + 1) * 32 + c];
            const float4 w2 = sW4[(k4 * 4 + 2) * 32 + c];
            const float4 w3 = sW4[(k4 * 4 + 3) * 32 + c];
#pragma unroll
            for (int i = 0; i < 8; i++) {
                const float4 av = sAgg4[(r * 8 + i) * 32 + k4];  // broadcast
                acc[i][0] += av.x * w0.x + av.y * w1.x + av.z * w2.x + av.w * w3.x;
                acc[i][1] += av.x * w0.y + av.y * w1.y + av.z * w2.y + av.w * w3.y;
                acc[i][2] += av.x * w0.z + av.y * w1.z + av.z * w2.z + av.w * w3.z;
                acc[i][3] += av.x * w0.w + av.y * w1.w + av.z * w2.w + av.w * w3.w;
            }
        }

        const float4 bv = reinterpret_cast<const float4*>(b)[c];
        float4* out4 = reinterpret_cast<float4*>(out);
#pragma unroll
        for (int i = 0; i < 8; i++) {
            const int gm = node_lo + r * 8 + i;
            if (gm < n_nodes) {
                const float dw = sDeg[r * 8 + i];
                float4 o;
                o.x = acc[i][0] + dw * bv.x;
                o.y = acc[i][1] + dw * bv.y;
                o.z = acc[i][2] + dw * bv.z;
                o.w = acc[i][3] + dw * bv.w;
                out4[(size_t)gm * D4 + c] = o;
            }
        }
    }
}

// ---------------------------------------------------------------------------
extern "C" void kernel_launch(void* const* d_in, const int* in_sizes, int n_in,
                              void* d_out, int out_size) {
    const float* x    = (const float*)d_in[0];
    const float* W    = (const float*)d_in[1];
    const float* b    = (const float*)d_in[2];
    const float* ew   = (const float*)d_in[3];
    const int*   esrc = (const int*)d_in[4];
    const int*   edst = (const int*)d_in[5];
    float*       out  = (float*)d_out;

    const int n_nodes = in_sizes[0] / D;
    const int E       = in_sizes[4];

    cudaFuncSetAttribute(gc_fused_kernel,
                         cudaFuncAttributeMaxDynamicSharedMemorySize, SMEM_BYTES);

    const int nblk = (n_nodes + NB - 1) / NB;
    gc_fused_kernel<<<nblk, 256, SMEM_BYTES>>>(
        reinterpret_cast<const float4*>(x), W, b, ew, esrc, edst,
        out, n_nodes, E);
}